// round 1
// baseline (speedup 1.0000x reference)
#include <cuda_runtime.h>
#include <cstdint>

// Problem constants
#define B_    32
#define T_    1024
#define N_    1024
#define D_    256
#define WIN_  100
#define WPAD_ 128          // window padded to 128 for uniform lane mapping
#define KST_  132          // smem row stride (floats) for transposed K  (16B-aligned rows, avoids conflicts)
#define PST_  132          // smem row stride (floats) for probs
#define TT_   32           // query-tile per block
#define NTHREADS 256

// smem layout (floats): kt[D_*KST_] (aliased as vs[WIN_*D_] later) | qs[TT_*D_] | probs[TT_*PST_]
#define SMEM_FLOATS (D_*KST_ + TT_*D_ + TT_*PST_)
#define SMEM_BYTES  (SMEM_FLOATS * 4)

__global__ __launch_bounds__(NTHREADS, 1)
void attn_main(const float* __restrict__ Q, const float* __restrict__ K,
               const float* __restrict__ V, const int* __restrict__ prev_arr,
               float* __restrict__ out_res, float* __restrict__ out_align,
               float* __restrict__ out_max)
{
    extern __shared__ float smem[];
    float* kt    = smem;                       // D_*KST_ ; later reused as vs[j][d] (WIN_*D_ <= D_*KST_)
    float* qs    = smem + D_*KST_;             // TT_*D_
    float* probs = qs + TT_*D_;                // TT_*PST_

    const int b    = blockIdx.y;
    const int t0   = blockIdx.x * TT_;
    const int tid  = threadIdx.x;
    const int warp = tid >> 5;
    const int lane = tid & 31;
    const int prev = prev_arr[b];

    const float* Qb = Q + ((size_t)b*T_ + t0) * D_;
    const float* Kw = K + ((size_t)b*N_ + prev) * D_;
    const float* Vw = V + ((size_t)b*N_ + prev) * D_;

    // ---- Load Q tile (32x256 f32), coalesced float4 ----
    {
        const float4* src = (const float4*)Qb;
        float4* dst = (float4*)qs;
        #pragma unroll
        for (int i = 0; i < (TT_*D_/4)/NTHREADS; i++)
            dst[tid + NTHREADS*i] = src[tid + NTHREADS*i];
    }

    // ---- Load K window transposed: kt[d*KST_ + j] = K[prev+j][d], rows j>=WIN_ zeroed ----
    for (int j = warp; j < WPAD_; j += 8) {
        if (j < WIN_) {
            const float* kr = Kw + (size_t)j * D_;
            #pragma unroll
            for (int i = 0; i < 8; i++) {
                int d = lane + 32*i;             // coalesced gmem read; ~4-way smem write conflict (cheap)
                kt[d*KST_ + j] = kr[d];
            }
        } else {
            #pragma unroll
            for (int i = 0; i < 8; i++)
                kt[(lane + 32*i)*KST_ + j] = 0.f;
        }
    }
    __syncthreads();

    // ---- Scores: warp handles 4 query rows (t = 4*warp..), lane handles j = 4*lane..4*lane+3 ----
    const int trow = warp * 4;
    float acc[4][4];
    #pragma unroll
    for (int tt = 0; tt < 4; tt++)
        #pragma unroll
        for (int jj = 0; jj < 4; jj++) acc[tt][jj] = 0.f;

    #pragma unroll 4
    for (int d = 0; d < D_; d++) {
        float4 k4 = *(const float4*)(kt + d*KST_ + 4*lane);   // conflict-free (consecutive 16B)
        float q0 = qs[(trow+0)*D_ + d];                        // smem broadcast
        float q1 = qs[(trow+1)*D_ + d];
        float q2 = qs[(trow+2)*D_ + d];
        float q3 = qs[(trow+3)*D_ + d];
        acc[0][0] += q0*k4.x; acc[0][1] += q0*k4.y; acc[0][2] += q0*k4.z; acc[0][3] += q0*k4.w;
        acc[1][0] += q1*k4.x; acc[1][1] += q1*k4.y; acc[1][2] += q1*k4.z; acc[1][3] += q1*k4.w;
        acc[2][0] += q2*k4.x; acc[2][1] += q2*k4.y; acc[2][2] += q2*k4.z; acc[2][3] += q2*k4.w;
        acc[3][0] += q3*k4.x; acc[3][1] += q3*k4.y; acc[3][2] += q3*k4.z; acc[3][3] += q3*k4.w;
    }
    const float scale = 0.0625f;   // rsqrt(256)
    #pragma unroll
    for (int tt = 0; tt < 4; tt++) {
        float4 s4 = make_float4(acc[tt][0]*scale, acc[tt][1]*scale,
                                acc[tt][2]*scale, acc[tt][3]*scale);
        *(float4*)(probs + (trow+tt)*PST_ + 4*lane) = s4;
    }
    __syncthreads();   // kt reads done -> safe to reuse as V buffer

    // ---- Load V window (row-major) into the kt buffer ----
    {
        const float4* src = (const float4*)Vw;
        float4* dst = (float4*)kt;                 // vs[j][d]
        for (int i = tid; i < (WIN_*D_)/4; i += NTHREADS)
            dst[i] = src[i];
    }

    // ---- Softmax + argmax (warp-local: each warp owns its 4 rows) ----
    #pragma unroll
    for (int tt = 0; tt < 4; tt++) {
        int t = trow + tt;
        float4 p4 = *(const float4*)(probs + t*PST_ + 4*lane);
        float v_[4] = {p4.x, p4.y, p4.z, p4.w};
        int jb = 4*lane;

        float mx = -3.4e38f;
        #pragma unroll
        for (int i = 0; i < 4; i++)
            if (jb + i < WIN_) mx = fmaxf(mx, v_[i]);
        #pragma unroll
        for (int off = 16; off; off >>= 1)
            mx = fmaxf(mx, __shfl_xor_sync(0xffffffffu, mx, off));

        float e_[4]; float s = 0.f;
        #pragma unroll
        for (int i = 0; i < 4; i++) {
            e_[i] = (jb + i < WIN_) ? __expf(v_[i] - mx) : 0.f;
            s += e_[i];
        }
        #pragma unroll
        for (int off = 16; off; off >>= 1)
            s += __shfl_xor_sync(0xffffffffu, s, off);
        float inv = 1.f / s;

        float pr[4];
        #pragma unroll
        for (int i = 0; i < 4; i++) pr[i] = e_[i] * inv;

        // argmax on final probabilities, first-occurrence tie rule (matches jnp.argmax)
        float bm = -1.f; int bi = N_;
        #pragma unroll
        for (int i = 0; i < 4; i++) {
            if (pr[i] > bm) { bm = pr[i]; bi = jb + i; }
        }
        #pragma unroll
        for (int off = 16; off; off >>= 1) {
            float om = __shfl_xor_sync(0xffffffffu, bm, off);
            int   oi = __shfl_xor_sync(0xffffffffu, bi, off);
            if (om > bm || (om == bm && oi < bi)) { bm = om; bi = oi; }
        }
        if (lane == 0)
            out_max[(size_t)b*T_ + t0 + t] = (float)(prev + bi);

        *(float4*)(probs + t*PST_ + 4*lane) = make_float4(pr[0], pr[1], pr[2], pr[3]);
    }
    __syncthreads();   // probs final, V loaded

    // ---- Alignments band write: alignments[b][prev+j][t0+lane] = probs[lane][j]  (coalesced 128B) ----
    for (int j = warp; j < WIN_; j += 8) {
        out_align[((size_t)b*N_ + prev + j)*T_ + t0 + lane] = probs[lane*PST_ + j];
    }

    // ---- PV: warp owns 4 rows; lane owns d = {4*lane..} and {128+4*lane..} ----
    const float* vs = kt;
    float ra[4][4], rb[4][4];
    #pragma unroll
    for (int tt = 0; tt < 4; tt++)
        #pragma unroll
        for (int i = 0; i < 4; i++) { ra[tt][i] = 0.f; rb[tt][i] = 0.f; }

    #pragma unroll 2
    for (int j = 0; j < WIN_; j++) {
        float4 va = *(const float4*)(vs + (size_t)j*D_ + 4*lane);
        float4 vb = *(const float4*)(vs + (size_t)j*D_ + 128 + 4*lane);
        float p0 = probs[(trow+0)*PST_ + j];
        float p1 = probs[(trow+1)*PST_ + j];
        float p2 = probs[(trow+2)*PST_ + j];
        float p3 = probs[(trow+3)*PST_ + j];
        ra[0][0]+=p0*va.x; ra[0][1]+=p0*va.y; ra[0][2]+=p0*va.z; ra[0][3]+=p0*va.w;
        rb[0][0]+=p0*vb.x; rb[0][1]+=p0*vb.y; rb[0][2]+=p0*vb.z; rb[0][3]+=p0*vb.w;
        ra[1][0]+=p1*va.x; ra[1][1]+=p1*va.y; ra[1][2]+=p1*va.z; ra[1][3]+=p1*va.w;
        rb[1][0]+=p1*vb.x; rb[1][1]+=p1*vb.y; rb[1][2]+=p1*vb.z; rb[1][3]+=p1*vb.w;
        ra[2][0]+=p2*va.x; ra[2][1]+=p2*va.y; ra[2][2]+=p2*va.z; ra[2][3]+=p2*va.w;
        rb[2][0]+=p2*vb.x; rb[2][1]+=p2*vb.y; rb[2][2]+=p2*vb.z; rb[2][3]+=p2*vb.w;
        ra[3][0]+=p3*va.x; ra[3][1]+=p3*va.y; ra[3][2]+=p3*va.z; ra[3][3]+=p3*va.w;
        rb[3][0]+=p3*vb.x; rb[3][1]+=p3*vb.y; rb[3][2]+=p3*vb.z; rb[3][3]+=p3*vb.w;
    }

    // ---- result = concat(PV, Q): [b][t][0:256]=PV, [256:512]=Q ----
    #pragma unroll
    for (int tt = 0; tt < 4; tt++) {
        int t = trow + tt;
        size_t row = ((size_t)b*T_ + t0 + t) * (2*D_);
        *(float4*)(out_res + row +           4*lane) = make_float4(ra[tt][0], ra[tt][1], ra[tt][2], ra[tt][3]);
        *(float4*)(out_res + row + 128     + 4*lane) = make_float4(rb[tt][0], rb[tt][1], rb[tt][2], rb[tt][3]);
        float4 qa = *(const float4*)(qs + (size_t)t*D_ +       4*lane);
        float4 qb = *(const float4*)(qs + (size_t)t*D_ + 128 + 4*lane);
        *(float4*)(out_res + row + 256     + 4*lane) = qa;
        *(float4*)(out_res + row + 256+128 + 4*lane) = qb;
    }
}

extern "C" void kernel_launch(void* const* d_in, const int* in_sizes, int n_in,
                              void* d_out, int out_size)
{
    const float* Q    = (const float*)d_in[0];
    const float* K    = (const float*)d_in[1];
    const float* V    = (const float*)d_in[2];
    const int*   prev = (const int*)d_in[3];

    float* out       = (float*)d_out;
    float* out_res   = out;                                   // B*T*2D
    float* out_align = out + (size_t)B_*T_*2*D_;              // B*N*T
    float* out_max   = out_align + (size_t)B_*N_*T_;          // B*T

    // zero alignments (masked positions are exactly 0); main kernel overwrites the 100-row band
    cudaMemsetAsync(out_align, 0, (size_t)B_*N_*T_*sizeof(float), 0);

    cudaFuncSetAttribute(attn_main, cudaFuncAttributeMaxDynamicSharedMemorySize, SMEM_BYTES);
    dim3 grid(T_/TT_, B_);
    attn_main<<<grid, NTHREADS, SMEM_BYTES>>>(Q, K, V, prev, out_res, out_align, out_max);
}

// round 2
// speedup vs baseline: 1.1418x; 1.1418x over previous
#include <cuda_runtime.h>
#include <cstdint>

#define B_    32
#define T_    1024
#define N_    1024
#define D_    256
#define WIN_  100
#define TT_   32           // query-tile per block
#define NTHREADS 256

#define KST 132            // kbuf row stride (floats): 128 data + 4 pad
#define QST 132            // qsT row stride
#define PST 33             // probsT stride: [j][t], conflict-free column stores

// smem (floats): kbuf[100*KST] | qsT[64*QST] | prT[128*PST]
#define KBUF_F   (100*KST)
#define QST_F    (64*QST)
#define PRT_F    (128*PST)
#define SMEM_FLOATS (KBUF_F + QST_F + PRT_F)
#define SMEM_BYTES  (SMEM_FLOATS * 4)

typedef unsigned long long ull;

__device__ __forceinline__ void fma2(ull& acc, ull a, ull b) {
    asm("fma.rn.f32x2 %0, %1, %2, %0;" : "+l"(acc) : "l"(a), "l"(b));
}
__device__ __forceinline__ ull pack2(float lo, float hi) {
    ull r; asm("mov.b64 %0, {%1, %2};" : "=l"(r) : "f"(lo), "f"(hi)); return r;
}
__device__ __forceinline__ float lo2(ull v) {
    float a, b; asm("mov.b64 {%0, %1}, %2;" : "=f"(a), "=f"(b) : "l"(v)); return a;
}
__device__ __forceinline__ float hi2(ull v) {
    float a, b; asm("mov.b64 {%0, %1}, %2;" : "=f"(a), "=f"(b) : "l"(v)); return b;
}

// load 100 rows x 128 floats (d-half h) of a row-major [N][256] window into dst[j*KST + d']
__device__ __forceinline__ void load_half(float* dst, const float* src, int h, int tid) {
    #pragma unroll
    for (int i = 0; i < 13; i++) {
        int idx = tid + NTHREADS * i;            // over 100*32 float4
        if (idx < 100*32) {
            int j = idx >> 5, c = idx & 31;
            float4 v = *(const float4*)(src + (size_t)j*D_ + 128*h + 4*c);
            *(float4*)(dst + j*KST + 4*c) = v;
        }
    }
}

__global__ __launch_bounds__(NTHREADS, 2)
void attn_main(const float* __restrict__ Q, const float* __restrict__ K,
               const float* __restrict__ V, const int* __restrict__ prev_arr,
               float* __restrict__ out_res, float* __restrict__ out_align,
               float* __restrict__ out_max)
{
    extern __shared__ float sm[];
    float* kbuf = sm;                  // [100][KST]  K half, later V half
    float* qsT  = sm + KBUF_F;         // [64][QST]: row r=d/4, entry t*4+c
    float* prT  = qsT + QST_F;         // [128][PST]: scores/probs transposed [j][t]

    const int b    = blockIdx.y;
    const int t0   = blockIdx.x * TT_;
    const int tid  = threadIdx.x;
    const int warp = tid >> 5;
    const int lane = tid & 31;
    const int prev = prev_arr[b];

    const float* Qb = Q + ((size_t)b*T_ + t0) * D_;
    const float* Kw = K + ((size_t)b*N_ + prev) * D_;
    const float* Vw = V + ((size_t)b*N_ + prev) * D_;

    // ---- Load Q tile into qsT[d/4][t*4 + c] ----
    #pragma unroll
    for (int i = 0; i < 8; i++) {
        int idx = tid + NTHREADS * i;            // 32*64 float4
        int t = idx >> 6, c = idx & 63;
        float4 q = ((const float4*)Qb)[idx];
        *(float4*)(qsT + c*QST + t*4) = q;
    }
    // ---- Load K d-half 0 ----
    load_half(kbuf, Kw, 0, tid);
    __syncthreads();

    // ================= QK: warp owns j in [16w,16w+16), lane owns t =================
    const int jw = warp * 16;
    ull acc2[16];
    #pragma unroll
    for (int i = 0; i < 16; i++) acc2[i] = 0ull;

    #pragma unroll 1
    for (int pass = 0; pass < 2; pass++) {
        #pragma unroll 2
        for (int d4 = 0; d4 < 32; d4++) {
            ulonglong2 q2 = *(const ulonglong2*)(qsT + (32*pass + d4)*QST + 4*lane);
            #pragma unroll
            for (int i = 0; i < 16; i++) {
                ulonglong2 k2 = *(const ulonglong2*)(kbuf + (jw + i)*KST + 4*d4);
                fma2(acc2[i], q2.x, k2.x);
                fma2(acc2[i], q2.y, k2.y);
            }
        }
        if (pass == 0) {
            __syncthreads();
            load_half(kbuf, Kw, 1, tid);
            __syncthreads();
        }
    }
    // reduce pairs, scale, store transposed scores (conflict-free: consecutive lanes)
    const float scale = 0.0625f;
    #pragma unroll
    for (int i = 0; i < 16; i++)
        prT[(jw + i)*PST + lane] = (lo2(acc2[i]) + hi2(acc2[i])) * scale;
    __syncthreads();

    // ================= Softmax + argmax: warp owns rows t in [4w,4w+4) ==============
    const int trow = warp * 4;
    #pragma unroll
    for (int tt = 0; tt < 4; tt++) {
        int t = trow + tt;
        int jb = 4 * lane;
        float v_[4];
        #pragma unroll
        for (int i = 0; i < 4; i++) v_[i] = prT[(jb + i)*PST + t];

        float mx = -3.4e38f;
        #pragma unroll
        for (int i = 0; i < 4; i++)
            if (jb + i < WIN_) mx = fmaxf(mx, v_[i]);
        #pragma unroll
        for (int off = 16; off; off >>= 1)
            mx = fmaxf(mx, __shfl_xor_sync(0xffffffffu, mx, off));

        float e_[4]; float s = 0.f;
        #pragma unroll
        for (int i = 0; i < 4; i++) {
            e_[i] = (jb + i < WIN_) ? __expf(v_[i] - mx) : 0.f;
            s += e_[i];
        }
        #pragma unroll
        for (int off = 16; off; off >>= 1)
            s += __shfl_xor_sync(0xffffffffu, s, off);
        float inv = 1.f / s;

        float pr[4];
        #pragma unroll
        for (int i = 0; i < 4; i++) pr[i] = e_[i] * inv;

        float bm = -1.f; int bi = N_;
        #pragma unroll
        for (int i = 0; i < 4; i++)
            if (pr[i] > bm) { bm = pr[i]; bi = jb + i; }
        #pragma unroll
        for (int off = 16; off; off >>= 1) {
            float om = __shfl_xor_sync(0xffffffffu, bm, off);
            int   oi = __shfl_xor_sync(0xffffffffu, bi, off);
            if (om > bm || (om == bm && oi < bi)) { bm = om; bi = oi; }
        }
        if (lane == 0)
            out_max[(size_t)b*T_ + t0 + t] = (float)(prev + bi);

        #pragma unroll
        for (int i = 0; i < 4; i++) prT[(jb + i)*PST + t] = pr[i];
    }

    // ---- Load V d-half 0 (kbuf free: QK reads done before last sync) ----
    load_half(kbuf, Vw, 0, tid);
    __syncthreads();

    // ================= PV: warp owns d-chunk [16w,16w+16) within half, lane owns t ===
    #pragma unroll 1
    for (int pass = 0; pass < 2; pass++) {
        const int dw = warp * 16;
        ull pv[8];
        #pragma unroll
        for (int i = 0; i < 8; i++) pv[i] = 0ull;

        #pragma unroll 2
        for (int j = 0; j < WIN_; j++) {
            float pb = prT[j*PST + lane];
            ull pp = pack2(pb, pb);
            const float* vr = kbuf + j*KST + dw;
            ulonglong2 v0 = *(const ulonglong2*)(vr);
            ulonglong2 v1 = *(const ulonglong2*)(vr + 4);
            ulonglong2 v2 = *(const ulonglong2*)(vr + 8);
            ulonglong2 v3 = *(const ulonglong2*)(vr + 12);
            fma2(pv[0], pp, v0.x); fma2(pv[1], pp, v0.y);
            fma2(pv[2], pp, v1.x); fma2(pv[3], pp, v1.y);
            fma2(pv[4], pp, v2.x); fma2(pv[5], pp, v2.y);
            fma2(pv[6], pp, v3.x); fma2(pv[7], pp, v3.y);
        }
        // store 16 floats of out_res row (b, t0+lane), global d = 128*pass + dw
        size_t row = ((size_t)b*T_ + t0 + lane) * (2*D_);
        float* dst = out_res + row + 128*pass + dw;
        #pragma unroll
        for (int c = 0; c < 4; c++) {
            float4 o = make_float4(lo2(pv[2*c]), hi2(pv[2*c]),
                                   lo2(pv[2*c+1]), hi2(pv[2*c+1]));
            *(float4*)(dst + 4*c) = o;
        }

        if (pass == 0) {
            // ---- Alignments: full columns (zeros outside the band), coalesced ----
            #pragma unroll 1
            for (int j = warp; j < N_; j += 8) {
                int jj = j - prev;
                float val = (jj >= 0 && jj < WIN_) ? prT[jj*PST + lane] : 0.f;
                out_align[((size_t)b*N_ + j)*T_ + t0 + lane] = val;
            }
            // ---- result[...,256:512] = Q (coalesced copy) ----
            #pragma unroll
            for (int i = 0; i < 8; i++) {
                int idx = tid + NTHREADS * i;
                int t = idx >> 6, c = idx & 63;
                float4 q = ((const float4*)Qb)[idx];
                ((float4*)out_res)[((size_t)b*T_ + t0 + t)*128 + 64 + c] = q;
            }
            __syncthreads();
            load_half(kbuf, Vw, 1, tid);
            __syncthreads();
        }
    }
}

extern "C" void kernel_launch(void* const* d_in, const int* in_sizes, int n_in,
                              void* d_out, int out_size)
{
    const float* Q    = (const float*)d_in[0];
    const float* K    = (const float*)d_in[1];
    const float* V    = (const float*)d_in[2];
    const int*   prev = (const int*)d_in[3];

    float* out       = (float*)d_out;
    float* out_res   = out;                                   // B*T*2D
    float* out_align = out + (size_t)B_*T_*2*D_;              // B*N*T
    float* out_max   = out_align + (size_t)B_*N_*T_;          // B*T

    cudaFuncSetAttribute(attn_main, cudaFuncAttributeMaxDynamicSharedMemorySize, SMEM_BYTES);
    dim3 grid(T_/TT_, B_);
    attn_main<<<grid, NTHREADS, SMEM_BYTES>>>(Q, K, V, prev, out_res, out_align, out_max);
}

// round 3
// speedup vs baseline: 1.2573x; 1.1012x over previous
#include <cuda_runtime.h>
#include <cstdint>

#define B_    32
#define T_    1024
#define N_    1024
#define D_    256
#define WIN_  100
#define TT_   64           // query-tile per block
#define NTHREADS 512

#define KST 132            // kbuf row stride (floats)
#define QROW 260           // qsT row stride (floats): 64 t * 4 + 16B pad
#define PST 65             // prT row stride: [j][t], 64 t + 1 pad

#define KBUF_F (100*KST)           // 13200
#define QST_F  (64*QROW)           // 16640
#define PRT_F  (128*PST)           // 8320
#define SMEM_FLOATS (KBUF_F + QST_F + PRT_F)
#define SMEM_BYTES  (SMEM_FLOATS * 4)   // 152640 B

typedef unsigned long long ull;

__device__ __forceinline__ void fma2(ull& acc, ull a, ull b) {
    asm("fma.rn.f32x2 %0, %1, %2, %0;" : "+l"(acc) : "l"(a), "l"(b));
}
__device__ __forceinline__ ull pack2(float lo, float hi) {
    ull r; asm("mov.b64 %0, {%1, %2};" : "=l"(r) : "f"(lo), "f"(hi)); return r;
}
__device__ __forceinline__ float lo2(ull v) {
    float a, b; asm("mov.b64 {%0, %1}, %2;" : "=f"(a), "=f"(b) : "l"(v)); return a;
}
__device__ __forceinline__ float hi2(ull v) {
    float a, b; asm("mov.b64 {%0, %1}, %2;" : "=f"(a), "=f"(b) : "l"(v)); return b;
}

// load 100 rows x 128 floats (d-half h) of row-major [N][256] window into dst[j*KST + d']
__device__ __forceinline__ void load_half(float* dst, const float* src, int h, int tid) {
    #pragma unroll
    for (int i = 0; i < 7; i++) {
        int idx = tid + NTHREADS * i;            // over 100*32 float4
        if (idx < 100*32) {
            int j = idx >> 5, c = idx & 31;
            float4 v = *(const float4*)(src + (size_t)j*D_ + 128*h + 4*c);
            *(float4*)(dst + j*KST + 4*c) = v;
        }
    }
}

__global__ __launch_bounds__(NTHREADS, 1)
void attn_main(const float* __restrict__ Q, const float* __restrict__ K,
               const float* __restrict__ V, const int* __restrict__ prev_arr,
               float* __restrict__ out_res, float* __restrict__ out_align,
               float* __restrict__ out_max)
{
    extern __shared__ float sm[];
    float* kbuf = sm;                  // [100][KST]  K half, later V half
    float* qsT  = sm + KBUF_F;         // [64 d4][t*4+c]
    float* prT  = qsT + QST_F;         // [128 j][PST]

    const int b    = blockIdx.y;
    const int t0   = blockIdx.x * TT_;
    const int tid  = threadIdx.x;
    const int warp = tid >> 5;         // 0..15
    const int lane = tid & 31;
    const int prev = prev_arr[b];

    const float* Qb = Q + ((size_t)b*T_ + t0) * D_;
    const float* Kw = K + ((size_t)b*N_ + prev) * D_;
    const float* Vw = V + ((size_t)b*N_ + prev) * D_;

    // ---- Load Q tile into qsT[d4][t*4+c] (64 t x 256 d) ----
    #pragma unroll
    for (int i = 0; i < 8; i++) {
        int idx = tid + NTHREADS * i;            // 64*64 float4
        int t = idx >> 6, c = idx & 63;
        float4 q = ((const float4*)Qb)[idx];
        *(float4*)(qsT + c*QROW + t*4) = q;
    }
    load_half(kbuf, Kw, 0, tid);
    __syncthreads();

    // ================= QK: warp owns j in [8w, 8w+8), lane owns t={lane, lane+32} ===
    const int jw = warp * 8;
    ull acc2[8][2];
    #pragma unroll
    for (int i = 0; i < 8; i++) { acc2[i][0] = 0ull; acc2[i][1] = 0ull; }

    #pragma unroll 1
    for (int pass = 0; pass < 2; pass++) {
        #pragma unroll 2
        for (int d4 = 0; d4 < 32; d4++) {
            const float* qr = qsT + (32*pass + d4)*QROW;
            ulonglong2 qa = *(const ulonglong2*)(qr + 4*lane);         // t = lane
            ulonglong2 qb = *(const ulonglong2*)(qr + 128 + 4*lane);   // t = lane+32
            #pragma unroll
            for (int i = 0; i < 8; i++) {
                ulonglong2 k2 = *(const ulonglong2*)(kbuf + (jw + i)*KST + 4*d4);
                fma2(acc2[i][0], qa.x, k2.x);
                fma2(acc2[i][0], qa.y, k2.y);
                fma2(acc2[i][1], qb.x, k2.x);
                fma2(acc2[i][1], qb.y, k2.y);
            }
        }
        if (pass == 0) {
            __syncthreads();
            load_half(kbuf, Kw, 1, tid);
            __syncthreads();
        }
    }
    const float scale = 0.0625f;
    #pragma unroll
    for (int i = 0; i < 8; i++) {
        prT[(jw + i)*PST + lane]      = (lo2(acc2[i][0]) + hi2(acc2[i][0])) * scale;
        prT[(jw + i)*PST + 32 + lane] = (lo2(acc2[i][1]) + hi2(acc2[i][1])) * scale;
    }
    __syncthreads();

    // ---- kbuf free: start V half-0 load now, its latency hides under softmax ----
    load_half(kbuf, Vw, 0, tid);

    // ================= Softmax + argmax: warp owns rows t in [4w, 4w+4) =============
    const int trow = warp * 4;
    #pragma unroll
    for (int tt = 0; tt < 4; tt++) {
        int t = trow + tt;
        float v_[4];
        #pragma unroll
        for (int i = 0; i < 4; i++) v_[i] = prT[(lane + 32*i)*PST + t];   // conflict-free

        float mx = -3.4e38f;
        #pragma unroll
        for (int i = 0; i < 4; i++)
            if (lane + 32*i < WIN_) mx = fmaxf(mx, v_[i]);
        #pragma unroll
        for (int off = 16; off; off >>= 1)
            mx = fmaxf(mx, __shfl_xor_sync(0xffffffffu, mx, off));

        float e_[4]; float s = 0.f;
        #pragma unroll
        for (int i = 0; i < 4; i++) {
            e_[i] = (lane + 32*i < WIN_) ? __expf(v_[i] - mx) : 0.f;
            s += e_[i];
        }
        #pragma unroll
        for (int off = 16; off; off >>= 1)
            s += __shfl_xor_sync(0xffffffffu, s, off);
        float inv = 1.f / s;

        float pr[4];
        #pragma unroll
        for (int i = 0; i < 4; i++) pr[i] = e_[i] * inv;

        // first-occurrence argmax over final probs (jnp.argmax tie rule)
        float bm = -1.f; int bi = N_;
        #pragma unroll
        for (int i = 0; i < 4; i++)
            if (pr[i] > bm) { bm = pr[i]; bi = lane + 32*i; }
        #pragma unroll
        for (int off = 16; off; off >>= 1) {
            float om = __shfl_xor_sync(0xffffffffu, bm, off);
            int   oi = __shfl_xor_sync(0xffffffffu, bi, off);
            if (om > bm || (om == bm && oi < bi)) { bm = om; bi = oi; }
        }
        if (lane == 0)
            out_max[(size_t)b*T_ + t0 + t] = (float)(prev + bi);

        #pragma unroll
        for (int i = 0; i < 4; i++) prT[(lane + 32*i)*PST + t] = pr[i];
    }
    __syncthreads();   // probs final, V half-0 loaded

    // ================= PV pass loop: warp owns d-chunk [8w, 8w+8) of half ===========
    const int dw = warp * 8;
    #pragma unroll 1
    for (int pass = 0; pass < 2; pass++) {
        ull pv[4][2];
        #pragma unroll
        for (int i = 0; i < 4; i++) { pv[i][0] = 0ull; pv[i][1] = 0ull; }

        #pragma unroll 2
        for (int j = 0; j < WIN_; j++) {
            float p0 = prT[j*PST + lane];
            float p1 = prT[j*PST + 32 + lane];
            ull pp0 = pack2(p0, p0);
            ull pp1 = pack2(p1, p1);
            const float* vr = kbuf + j*KST + dw;
            ulonglong2 va = *(const ulonglong2*)(vr);
            ulonglong2 vb = *(const ulonglong2*)(vr + 4);
            fma2(pv[0][0], pp0, va.x); fma2(pv[1][0], pp0, va.y);
            fma2(pv[2][0], pp0, vb.x); fma2(pv[3][0], pp0, vb.y);
            fma2(pv[0][1], pp1, va.x); fma2(pv[1][1], pp1, va.y);
            fma2(pv[2][1], pp1, vb.x); fma2(pv[3][1], pp1, vb.y);
        }
        #pragma unroll
        for (int tp = 0; tp < 2; tp++) {
            int t = lane + 32*tp;
            float* dst = out_res + ((size_t)b*T_ + t0 + t)*(2*D_) + 128*pass + dw;
            *(float4*)(dst)     = make_float4(lo2(pv[0][tp]), hi2(pv[0][tp]),
                                              lo2(pv[1][tp]), hi2(pv[1][tp]));
            *(float4*)(dst + 4) = make_float4(lo2(pv[2][tp]), hi2(pv[2][tp]),
                                              lo2(pv[3][tp]), hi2(pv[3][tp]));
        }

        if (pass == 0) {
            // ---- Alignments: full columns (zeros off-band), coalesced 128B stores ----
            #pragma unroll 1
            for (int j = warp; j < N_; j += 16) {
                int jj = j - prev;
                bool inb = (jj >= 0 && jj < WIN_);
                float v0 = inb ? prT[jj*PST + lane]      : 0.f;
                float v1 = inb ? prT[jj*PST + 32 + lane] : 0.f;
                float* ar = out_align + ((size_t)b*N_ + j)*T_ + t0;
                ar[lane]      = v0;
                ar[32 + lane] = v1;
            }
            // ---- result[...,256:512] = Q ----
            #pragma unroll
            for (int i = 0; i < 8; i++) {
                int idx = tid + NTHREADS * i;
                int t = idx >> 6, c = idx & 63;
                float4 q = ((const float4*)Qb)[idx];
                ((float4*)out_res)[((size_t)b*T_ + t0 + t)*128 + 64 + c] = q;
            }
            __syncthreads();
            load_half(kbuf, Vw, 1, tid);
            __syncthreads();
        }
    }
}

extern "C" void kernel_launch(void* const* d_in, const int* in_sizes, int n_in,
                              void* d_out, int out_size)
{
    const float* Q    = (const float*)d_in[0];
    const float* K    = (const float*)d_in[1];
    const float* V    = (const float*)d_in[2];
    const int*   prev = (const int*)d_in[3];

    float* out       = (float*)d_out;
    float* out_res   = out;                                   // B*T*2D
    float* out_align = out + (size_t)B_*T_*2*D_;              // B*N*T
    float* out_max   = out_align + (size_t)B_*N_*T_;          // B*T

    cudaFuncSetAttribute(attn_main, cudaFuncAttributeMaxDynamicSharedMemorySize, SMEM_BYTES);
    dim3 grid(T_/TT_, B_);
    attn_main<<<grid, NTHREADS, SMEM_BYTES>>>(Q, K, V, prev, out_res, out_align, out_max);
}